// round 1
// baseline (speedup 1.0000x reference)
#include <cuda_runtime.h>
#include <cuda_bf16.h>
#include <cooperative_groups.h>
#include <math.h>

namespace cg = cooperative_groups;

#define BB   32
#define NN_  400
#define TT   315
#define DD   512
#define HH   256

// ---------------- scratch (static device globals; no allocations) ----------------
__device__ float g_tA[TT * DD];           // text @ A^T                [T, D]
__device__ float g_s [BB * NN_ * TT];     // affinity / sinkhorn s1    [B, N, T]
__device__ float g_f1[BB * TT * DD];      // mixed features            [B, T, D]
__device__ float g_th[TT * HH];           // text @ Wh_bottom          [T, H]
__device__ float g_h [BB * TT * HH];      // hidden                    [B*T, H]

// ============================================================================
// NT GEMM: C[M,N] = A[M,K](row,k-contig) * B[N,K](row,k-contig)^T
// 64x64 tile, BK=16, 256 threads, 4x4 per thread. Requires K % 16 == 0.
// ============================================================================
__global__ void gemm_nt_kernel(const float* __restrict__ A, const float* __restrict__ B,
                               float* __restrict__ C, int M, int N, int K, int ldc) {
    __shared__ float As[16][65];
    __shared__ float Bs[16][65];
    const int bm = blockIdx.x * 64, bn = blockIdx.y * 64;
    const int tid = threadIdx.x;
    const int tm = tid >> 4, tn = tid & 15;
    const int lr = tid >> 2;            // 0..63
    const int lc = (tid & 3) << 2;      // 0,4,8,12
    const bool okA = (bm + lr) < M;
    const bool okB = (bn + lr) < N;

    float acc[4][4];
#pragma unroll
    for (int i = 0; i < 4; i++)
#pragma unroll
        for (int j = 0; j < 4; j++) acc[i][j] = 0.f;

    for (int k0 = 0; k0 < K; k0 += 16) {
        float4 av = make_float4(0.f, 0.f, 0.f, 0.f);
        float4 bv = make_float4(0.f, 0.f, 0.f, 0.f);
        if (okA) av = *(const float4*)(A + (size_t)(bm + lr) * K + k0 + lc);
        if (okB) bv = *(const float4*)(B + (size_t)(bn + lr) * K + k0 + lc);
        __syncthreads();
        As[lc + 0][lr] = av.x; As[lc + 1][lr] = av.y; As[lc + 2][lr] = av.z; As[lc + 3][lr] = av.w;
        Bs[lc + 0][lr] = bv.x; Bs[lc + 1][lr] = bv.y; Bs[lc + 2][lr] = bv.z; Bs[lc + 3][lr] = bv.w;
        __syncthreads();
#pragma unroll
        for (int kk = 0; kk < 16; kk++) {
            float a0 = As[kk][tm * 4 + 0], a1 = As[kk][tm * 4 + 1];
            float a2 = As[kk][tm * 4 + 2], a3 = As[kk][tm * 4 + 3];
            float b0 = Bs[kk][tn * 4 + 0], b1 = Bs[kk][tn * 4 + 1];
            float b2 = Bs[kk][tn * 4 + 2], b3 = Bs[kk][tn * 4 + 3];
            acc[0][0] += a0 * b0; acc[0][1] += a0 * b1; acc[0][2] += a0 * b2; acc[0][3] += a0 * b3;
            acc[1][0] += a1 * b0; acc[1][1] += a1 * b1; acc[1][2] += a1 * b2; acc[1][3] += a1 * b3;
            acc[2][0] += a2 * b0; acc[2][1] += a2 * b1; acc[2][2] += a2 * b2; acc[2][3] += a2 * b3;
            acc[3][0] += a3 * b0; acc[3][1] += a3 * b1; acc[3][2] += a3 * b2; acc[3][3] += a3 * b3;
        }
    }
#pragma unroll
    for (int i = 0; i < 4; i++) {
        int r = bm + tm * 4 + i;
        if (r >= M) continue;
#pragma unroll
        for (int j = 0; j < 4; j++) {
            int c = bn + tn * 4 + j;
            if (c < N) C[(size_t)r * ldc + c] = acc[i][j];
        }
    }
}

// ============================================================================
// TN GEMM (batched): C[M,N] = sum_k A[K,M](m-contig) * B[K,N](n-contig)
// Requires K % 16 == 0, N tile-exact float4-aligned rows (ldb % 4 == 0).
// ============================================================================
__global__ void gemm_tn_kernel(const float* __restrict__ A, const float* __restrict__ B,
                               float* __restrict__ C, int M, int N, int K,
                               int lda, int ldb, int ldc,
                               long long sA, long long sB, long long sC) {
    A += (long long)blockIdx.z * sA;
    B += (long long)blockIdx.z * sB;
    C += (long long)blockIdx.z * sC;
    __shared__ float As[16][64];
    __shared__ float Bs[16][64];
    const int bm = blockIdx.x * 64, bn = blockIdx.y * 64;
    const int tid = threadIdx.x;
    const int tm = tid >> 4, tn = tid & 15;
    const int kr = tid >> 4;            // 0..15
    const int nc4 = (tid & 15) << 2;    // 0..60

    float acc[4][4];
#pragma unroll
    for (int i = 0; i < 4; i++)
#pragma unroll
        for (int j = 0; j < 4; j++) acc[i][j] = 0.f;

    for (int k0 = 0; k0 < K; k0 += 16) {
        __syncthreads();
#pragma unroll
        for (int i = 0; i < 4; i++) {
            int e = tid + i * 256;
            int kk = e >> 6, mm = e & 63;
            float v = 0.f;
            if (bm + mm < M) v = A[(size_t)(k0 + kk) * lda + bm + mm];
            As[kk][mm] = v;
        }
        float4 bv = make_float4(0.f, 0.f, 0.f, 0.f);
        if (bn + nc4 < N) bv = *(const float4*)(B + (size_t)(k0 + kr) * ldb + bn + nc4);
        *(float4*)&Bs[kr][nc4] = bv;
        __syncthreads();
#pragma unroll
        for (int kk = 0; kk < 16; kk++) {
            float4 a = *(float4*)&As[kk][tm * 4];
            float4 b = *(float4*)&Bs[kk][tn * 4];
            acc[0][0] += a.x * b.x; acc[0][1] += a.x * b.y; acc[0][2] += a.x * b.z; acc[0][3] += a.x * b.w;
            acc[1][0] += a.y * b.x; acc[1][1] += a.y * b.y; acc[1][2] += a.y * b.z; acc[1][3] += a.y * b.w;
            acc[2][0] += a.z * b.x; acc[2][1] += a.z * b.y; acc[2][2] += a.z * b.z; acc[2][3] += a.z * b.w;
            acc[3][0] += a.w * b.x; acc[3][1] += a.w * b.y; acc[3][2] += a.w * b.z; acc[3][3] += a.w * b.w;
        }
    }
#pragma unroll
    for (int i = 0; i < 4; i++) {
        int r = bm + tm * 4 + i;
        if (r >= M) continue;
#pragma unroll
        for (int j = 0; j < 4; j++) {
            int c = bn + tn * 4 + j;
            if (c < N) C[(size_t)r * ldc + c] = acc[i][j];
        }
    }
}

// ============================================================================
// NN GEMM: C[M,N] = A[M,K](k-contig) * B[K,N](n-contig)
// EPI==1: C = relu(C + addrow[(m % TT)*N + n] + bias[n])
// Requires K % 16 == 0, ldb = N, N % 4 == 0, K rows of A float4-aligned.
// ============================================================================
template <int EPI>
__global__ void gemm_nn_kernel(const float* __restrict__ A, const float* __restrict__ B,
                               float* __restrict__ C, int M, int N, int K,
                               const float* __restrict__ addrow,
                               const float* __restrict__ bias) {
    __shared__ float As[16][65];
    __shared__ float Bs[16][64];
    const int bm = blockIdx.x * 64, bn = blockIdx.y * 64;
    const int tid = threadIdx.x;
    const int tm = tid >> 4, tn = tid & 15;
    const int lr = tid >> 2;
    const int lc = (tid & 3) << 2;
    const int kr = tid >> 4;
    const int nc4 = (tid & 15) << 2;
    const bool okA = (bm + lr) < M;
    const bool okB = (bn + nc4) < N;

    float acc[4][4];
#pragma unroll
    for (int i = 0; i < 4; i++)
#pragma unroll
        for (int j = 0; j < 4; j++) acc[i][j] = 0.f;

    for (int k0 = 0; k0 < K; k0 += 16) {
        float4 av = make_float4(0.f, 0.f, 0.f, 0.f);
        float4 bv = make_float4(0.f, 0.f, 0.f, 0.f);
        if (okA) av = *(const float4*)(A + (size_t)(bm + lr) * K + k0 + lc);
        if (okB) bv = *(const float4*)(B + (size_t)(k0 + kr) * N + bn + nc4);
        __syncthreads();
        As[lc + 0][lr] = av.x; As[lc + 1][lr] = av.y; As[lc + 2][lr] = av.z; As[lc + 3][lr] = av.w;
        *(float4*)&Bs[kr][nc4] = bv;
        __syncthreads();
#pragma unroll
        for (int kk = 0; kk < 16; kk++) {
            float a0 = As[kk][tm * 4 + 0], a1 = As[kk][tm * 4 + 1];
            float a2 = As[kk][tm * 4 + 2], a3 = As[kk][tm * 4 + 3];
            float4 b = *(float4*)&Bs[kk][tn * 4];
            acc[0][0] += a0 * b.x; acc[0][1] += a0 * b.y; acc[0][2] += a0 * b.z; acc[0][3] += a0 * b.w;
            acc[1][0] += a1 * b.x; acc[1][1] += a1 * b.y; acc[1][2] += a1 * b.z; acc[1][3] += a1 * b.w;
            acc[2][0] += a2 * b.x; acc[2][1] += a2 * b.y; acc[2][2] += a2 * b.z; acc[2][3] += a2 * b.w;
            acc[3][0] += a3 * b.x; acc[3][1] += a3 * b.y; acc[3][2] += a3 * b.z; acc[3][3] += a3 * b.w;
        }
    }
#pragma unroll
    for (int i = 0; i < 4; i++) {
        int r = bm + tm * 4 + i;
        if (r >= M) continue;
        int t = r % TT;
#pragma unroll
        for (int j = 0; j < 4; j++) {
            int c = bn + tn * 4 + j;
            if (c < N) {
                float v = acc[i][j];
                if (EPI) {
                    v += addrow[(size_t)t * N + c] + bias[c];
                    v = fmaxf(v, 0.f);
                }
                C[(size_t)r * N + c] = v;
            }
        }
    }
}

// ============================================================================
// Sinkhorn (exp-domain matrix scaling), fused InstanceNorm, persistent,
// 4-CTA cluster per batch element: 100 rows of E (100x315 fp32) per CTA in SMEM.
// ============================================================================
#define SINK_FLOATS 33584
#define SINK_SMEM   (SINK_FLOATS * 4)

__global__ void __cluster_dims__(4, 1, 1) __launch_bounds__(1024, 1)
sinkhorn_kernel(float* __restrict__ s, const float* __restrict__ gamma_p,
                const float* __restrict__ beta_p) {
    extern __shared__ float sm[];
    cg::cluster_group cluster = cg::this_cluster();
    const int tid  = threadIdx.x;
    const int wid  = tid >> 5;
    const int lane = tid & 31;
    const int crank = (int)cluster.block_rank();   // 0..3
    const int batch = blockIdx.x >> 2;

    float* E   = sm;                  // 31500
    float* Cv  = sm + 31500;          // 320
    float* RU  = sm + 31820;          // 104
    float* CP  = sm + 31924;          // 948
    float* LC  = sm + 32872;          // 640 (double-buffered 2x320)
    float* RED = sm + 33512;          // 64
    float* ST  = sm + 33576;          // 8

    float* gbase = s + (size_t)batch * NN_ * TT + (size_t)crank * 100 * TT;

    // ---- phase 0: load slice + stats ----
    float psum = 0.f, psq = 0.f;
    for (int row = wid; row < 100; row += 32) {
        const float* gr = gbase + row * TT;
        float* er = E + row * TT;
        for (int t = lane; t < TT; t += 32) {
            float v = gr[t];
            er[t] = v;
            psum += v;
            psq  += v * v;
        }
    }
#pragma unroll
    for (int o = 16; o; o >>= 1) {
        psum += __shfl_xor_sync(0xffffffffu, psum, o);
        psq  += __shfl_xor_sync(0xffffffffu, psq,  o);
    }
    if (lane == 0) { RED[wid] = psum; RED[32 + wid] = psq; }
    __syncthreads();
    if (wid == 0) {
        float a = RED[lane], b = RED[32 + lane];
#pragma unroll
        for (int o = 16; o; o >>= 1) {
            a += __shfl_xor_sync(0xffffffffu, a, o);
            b += __shfl_xor_sync(0xffffffffu, b, o);
        }
        if (lane == 0) { ST[0] = a; ST[1] = b; }
    }
    cluster.sync();
    if (tid == 0) {
        float S = 0.f, Q = 0.f;
#pragma unroll
        for (int c = 0; c < 4; c++) {
            const float* r = (const float*)cluster.map_shared_rank((void*)ST, c);
            S += r[0]; Q += r[1];
        }
        const float inv = 1.0f / (float)(NN_ * TT);
        float m   = S * inv;
        float var = Q * inv - m * m;
        float istd = rsqrtf(var + 1e-5f);
        ST[2] = m;
        ST[3] = gamma_p[0] * istd;
        ST[4] = beta_p[0];
    }
    __syncthreads();
    const float mean = ST[2], gi = ST[3], bta = ST[4];

    // ---- phase 1: E = exp(norm(s)) ; init column scaling to 1 ----
    for (int row = wid; row < 100; row += 32) {
        float* er = E + row * TT;
        for (int t = lane; t < TT; t += 32)
            er[t] = expf(fmaf(er[t] - mean, gi, bta));
    }
    if (tid < TT) Cv[tid] = 1.0f;
    __syncthreads();

    // ---- phase 2: 100 sinkhorn iterations ----
    for (int k = 0; k < 100; k++) {
        // row pass: ru[n] = 1 / sum_t E[n,t]*Cv[t]   (local rows)
        for (int row = wid; row < 100; row += 32) {
            const float* er = E + row * TT;
            float acc = 0.f;
            for (int t = lane; t < TT; t += 32) acc += er[t] * Cv[t];
#pragma unroll
            for (int o = 16; o; o >>= 1) acc += __shfl_xor_sync(0xffffffffu, acc, o);
            if (lane == 0) RU[row] = 1.0f / acc;
        }
        __syncthreads();
        // col pass partials over local rows (3 row-chunks per column)
        if (tid < 3 * TT) {
            int p = tid / TT;                 // 0..2
            int t = tid - p * TT;
            int r0 = (p == 0) ? 0 : (33 * p + 1);
            int r1 = r0 + ((p == 0) ? 34 : 33);
            float acc = 0.f;
            for (int n = r0; n < r1; n++) acc += E[n * TT + t] * RU[n];
            CP[p * TT + t] = acc;
        }
        __syncthreads();
        const int buf = (k & 1) * 320;
        if (tid < TT) LC[buf + tid] = CP[tid] + CP[TT + tid] + CP[2 * TT + tid];
        cluster.sync();
        if (tid < TT) {
            float tot = 0.f;
#pragma unroll
            for (int c = 0; c < 4; c++) {
                const float* r = (const float*)cluster.map_shared_rank((void*)LC, c);
                tot += r[buf + tid];
            }
            Cv[tid] = 1.0f / tot;
        }
        __syncthreads();
    }

    // ---- phase 3: write s1 = E * ru * cv ----
    for (int row = wid; row < 100; row += 32) {
        const float r = RU[row];
        const float* er = E + row * TT;
        float* gr = gbase + row * TT;
        for (int t = lane; t < TT; t += 32)
            gr[t] = er[t] * r * Cv[t];
    }
    cluster.sync();   // keep SMEM alive until all cluster reads are done
}

// ============================================================================
// head: pred[i] = sum_h h[i,h] * Wo[h] + bo    (one warp per output row)
// ============================================================================
__global__ void head_kernel(const float* __restrict__ h, const float* __restrict__ Wo,
                            const float* __restrict__ bo, float* __restrict__ out, int total) {
    int gwarp = (blockIdx.x * blockDim.x + threadIdx.x) >> 5;
    int lane = threadIdx.x & 31;
    if (gwarp >= total) return;
    const float* hp = h + (size_t)gwarp * HH;
    float acc = 0.f;
#pragma unroll
    for (int i = lane; i < HH; i += 32) acc += hp[i] * Wo[i];
#pragma unroll
    for (int o = 16; o; o >>= 1) acc += __shfl_xor_sync(0xffffffffu, acc, o);
    if (lane == 0) out[gwarp] = acc + bo[0];
}

// ============================================================================
extern "C" void kernel_launch(void* const* d_in, const int* in_sizes, int n_in,
                              void* d_out, int out_size) {
    (void)in_sizes; (void)n_in; (void)out_size;
    const float* features = (const float*)d_in[0];   // [B, N, D]
    const float* text     = (const float*)d_in[1];   // [T, D]
    const float* Amat     = (const float*)d_in[2];   // [D, D]
    const float* gamma    = (const float*)d_in[3];   // scalar
    const float* beta     = (const float*)d_in[4];   // scalar
    const float* Wh       = (const float*)d_in[5];   // [2D, H]
    const float* bh       = (const float*)d_in[6];   // [H]
    const float* Wo       = (const float*)d_in[7];   // [H, 1]
    const float* bo       = (const float*)d_in[8];   // [1]
    float* out = (float*)d_out;                      // [B, T]

    float *tA, *sbuf, *f1, *th, *hbuf;
    cudaGetSymbolAddress((void**)&tA,   g_tA);
    cudaGetSymbolAddress((void**)&sbuf, g_s);
    cudaGetSymbolAddress((void**)&f1,   g_f1);
    cudaGetSymbolAddress((void**)&th,   g_th);
    cudaGetSymbolAddress((void**)&hbuf, g_h);

    cudaFuncSetAttribute(sinkhorn_kernel,
                         cudaFuncAttributeMaxDynamicSharedMemorySize, SINK_SMEM);

    dim3 b256(256);

    // tA[t,d] = sum_e text[t,e] * A[d,e]
    gemm_nt_kernel<<<dim3((TT + 63) / 64, DD / 64), b256>>>(text, Amat, tA, TT, DD, DD, DD);

    // s[b*n, t] = sum_d features[b,n,d] * tA[t,d]
    gemm_nt_kernel<<<dim3((BB * NN_) / 64, (TT + 63) / 64), b256>>>(
        features, tA, sbuf, BB * NN_, TT, DD, TT);

    // instance-norm + 100 sinkhorn iterations, s -> s1 in place
    sinkhorn_kernel<<<BB * 4, 1024, SINK_SMEM>>>(sbuf, gamma, beta);

    // features1[b,t,d] = sum_n s1[b,n,t] * features[b,n,d]
    gemm_tn_kernel<<<dim3((TT + 63) / 64, DD / 64, BB), b256>>>(
        sbuf, features, f1, TT, DD, NN_, TT, DD, DD,
        (long long)NN_ * TT, (long long)NN_ * DD, (long long)TT * DD);

    // th[t,h] = sum_e text[t,e] * Wh[D+e, h]
    gemm_nn_kernel<0><<<dim3((TT + 63) / 64, HH / 64), b256>>>(
        text, Wh + (size_t)DD * HH, th, TT, HH, DD, nullptr, nullptr);

    // h = relu(f1 @ Wh_top + th + bh)
    gemm_nn_kernel<1><<<dim3((BB * TT + 63) / 64, HH / 64), b256>>>(
        f1, Wh, hbuf, BB * TT, HH, DD, th, bh);

    // pred = h @ Wo + bo
    head_kernel<<<(BB * TT * 32 + 255) / 256, 256>>>(hbuf, Wo, bo, out, BB * TT);
}

// round 2
// speedup vs baseline: 1.0005x; 1.0005x over previous
#include <cuda_runtime.h>
#include <cuda_bf16.h>
#include <cooperative_groups.h>
#include <math.h>

namespace cg = cooperative_groups;

#define BB   32
#define NN_  400
#define TT   315
#define DD   512
#define HH   256

// ---------------- scratch (static device globals; no allocations) ----------------
__device__ float g_tA[TT * DD];           // text @ A^T                [T, D]
__device__ float g_s [BB * NN_ * TT];     // affinity / sinkhorn s1    [B, N, T]
__device__ float g_f1[BB * TT * DD];      // mixed features            [B, T, D]
__device__ float g_th[TT * HH];           // text @ Wh_bottom          [T, H]
__device__ float g_h [BB * TT * HH];      // hidden                    [B*T, H]

// ============================================================================
// NT GEMM: C[M,N] = A[M,K](row,k-contig) * B[N,K](row,k-contig)^T
// 64x64 tile, BK=16, 256 threads, 4x4 per thread. Requires K % 16 == 0.
// ============================================================================
__global__ void gemm_nt_kernel(const float* __restrict__ A, const float* __restrict__ B,
                               float* __restrict__ C, int M, int N, int K, int ldc) {
    __shared__ float As[16][65];
    __shared__ float Bs[16][65];
    const int bm = blockIdx.x * 64, bn = blockIdx.y * 64;
    const int tid = threadIdx.x;
    const int tm = tid >> 4, tn = tid & 15;
    const int lr = tid >> 2;            // 0..63
    const int lc = (tid & 3) << 2;      // 0,4,8,12
    const bool okA = (bm + lr) < M;
    const bool okB = (bn + lr) < N;

    float acc[4][4];
#pragma unroll
    for (int i = 0; i < 4; i++)
#pragma unroll
        for (int j = 0; j < 4; j++) acc[i][j] = 0.f;

    for (int k0 = 0; k0 < K; k0 += 16) {
        float4 av = make_float4(0.f, 0.f, 0.f, 0.f);
        float4 bv = make_float4(0.f, 0.f, 0.f, 0.f);
        if (okA) av = *(const float4*)(A + (size_t)(bm + lr) * K + k0 + lc);
        if (okB) bv = *(const float4*)(B + (size_t)(bn + lr) * K + k0 + lc);
        __syncthreads();
        As[lc + 0][lr] = av.x; As[lc + 1][lr] = av.y; As[lc + 2][lr] = av.z; As[lc + 3][lr] = av.w;
        Bs[lc + 0][lr] = bv.x; Bs[lc + 1][lr] = bv.y; Bs[lc + 2][lr] = bv.z; Bs[lc + 3][lr] = bv.w;
        __syncthreads();
#pragma unroll
        for (int kk = 0; kk < 16; kk++) {
            float a0 = As[kk][tm * 4 + 0], a1 = As[kk][tm * 4 + 1];
            float a2 = As[kk][tm * 4 + 2], a3 = As[kk][tm * 4 + 3];
            float b0 = Bs[kk][tn * 4 + 0], b1 = Bs[kk][tn * 4 + 1];
            float b2 = Bs[kk][tn * 4 + 2], b3 = Bs[kk][tn * 4 + 3];
            acc[0][0] += a0 * b0; acc[0][1] += a0 * b1; acc[0][2] += a0 * b2; acc[0][3] += a0 * b3;
            acc[1][0] += a1 * b0; acc[1][1] += a1 * b1; acc[1][2] += a1 * b2; acc[1][3] += a1 * b3;
            acc[2][0] += a2 * b0; acc[2][1] += a2 * b1; acc[2][2] += a2 * b2; acc[2][3] += a2 * b3;
            acc[3][0] += a3 * b0; acc[3][1] += a3 * b1; acc[3][2] += a3 * b2; acc[3][3] += a3 * b3;
        }
    }
#pragma unroll
    for (int i = 0; i < 4; i++) {
        int r = bm + tm * 4 + i;
        if (r >= M) continue;
#pragma unroll
        for (int j = 0; j < 4; j++) {
            int c = bn + tn * 4 + j;
            if (c < N) C[(size_t)r * ldc + c] = acc[i][j];
        }
    }
}

// ============================================================================
// TN GEMM (batched): C[M,N] = sum_k A[K,M](m-contig) * B[K,N](n-contig)
// Requires K % 16 == 0, N tile-exact float4-aligned rows (ldb % 4 == 0).
// ============================================================================
__global__ void gemm_tn_kernel(const float* __restrict__ A, const float* __restrict__ B,
                               float* __restrict__ C, int M, int N, int K,
                               int lda, int ldb, int ldc,
                               long long sA, long long sB, long long sC) {
    A += (long long)blockIdx.z * sA;
    B += (long long)blockIdx.z * sB;
    C += (long long)blockIdx.z * sC;
    __shared__ float As[16][64];
    __shared__ float Bs[16][64];
    const int bm = blockIdx.x * 64, bn = blockIdx.y * 64;
    const int tid = threadIdx.x;
    const int tm = tid >> 4, tn = tid & 15;
    const int kr = tid >> 4;            // 0..15
    const int nc4 = (tid & 15) << 2;    // 0..60

    float acc[4][4];
#pragma unroll
    for (int i = 0; i < 4; i++)
#pragma unroll
        for (int j = 0; j < 4; j++) acc[i][j] = 0.f;

    for (int k0 = 0; k0 < K; k0 += 16) {
        __syncthreads();
#pragma unroll
        for (int i = 0; i < 4; i++) {
            int e = tid + i * 256;
            int kk = e >> 6, mm = e & 63;
            float v = 0.f;
            if (bm + mm < M) v = A[(size_t)(k0 + kk) * lda + bm + mm];
            As[kk][mm] = v;
        }
        float4 bv = make_float4(0.f, 0.f, 0.f, 0.f);
        if (bn + nc4 < N) bv = *(const float4*)(B + (size_t)(k0 + kr) * ldb + bn + nc4);
        *(float4*)&Bs[kr][nc4] = bv;
        __syncthreads();
#pragma unroll
        for (int kk = 0; kk < 16; kk++) {
            float4 a = *(float4*)&As[kk][tm * 4];
            float4 b = *(float4*)&Bs[kk][tn * 4];
            acc[0][0] += a.x * b.x; acc[0][1] += a.x * b.y; acc[0][2] += a.x * b.z; acc[0][3] += a.x * b.w;
            acc[1][0] += a.y * b.x; acc[1][1] += a.y * b.y; acc[1][2] += a.y * b.z; acc[1][3] += a.y * b.w;
            acc[2][0] += a.z * b.x; acc[2][1] += a.z * b.y; acc[2][2] += a.z * b.z; acc[2][3] += a.z * b.w;
            acc[3][0] += a.w * b.x; acc[3][1] += a.w * b.y; acc[3][2] += a.w * b.z; acc[3][3] += a.w * b.w;
        }
    }
#pragma unroll
    for (int i = 0; i < 4; i++) {
        int r = bm + tm * 4 + i;
        if (r >= M) continue;
#pragma unroll
        for (int j = 0; j < 4; j++) {
            int c = bn + tn * 4 + j;
            if (c < N) C[(size_t)r * ldc + c] = acc[i][j];
        }
    }
}

// ============================================================================
// NN GEMM: C[M,N] = A[M,K](k-contig) * B[K,N](n-contig)
// EPI==1: C = relu(C + addrow[(m % TT)*N + n] + bias[n])
// Requires K % 16 == 0, ldb = N, N % 4 == 0, K rows of A float4-aligned.
// ============================================================================
template <int EPI>
__global__ void gemm_nn_kernel(const float* __restrict__ A, const float* __restrict__ B,
                               float* __restrict__ C, int M, int N, int K,
                               const float* __restrict__ addrow,
                               const float* __restrict__ bias) {
    __shared__ float As[16][65];
    __shared__ float Bs[16][64];
    const int bm = blockIdx.x * 64, bn = blockIdx.y * 64;
    const int tid = threadIdx.x;
    const int tm = tid >> 4, tn = tid & 15;
    const int lr = tid >> 2;
    const int lc = (tid & 3) << 2;
    const int kr = tid >> 4;
    const int nc4 = (tid & 15) << 2;
    const bool okA = (bm + lr) < M;
    const bool okB = (bn + nc4) < N;

    float acc[4][4];
#pragma unroll
    for (int i = 0; i < 4; i++)
#pragma unroll
        for (int j = 0; j < 4; j++) acc[i][j] = 0.f;

    for (int k0 = 0; k0 < K; k0 += 16) {
        float4 av = make_float4(0.f, 0.f, 0.f, 0.f);
        float4 bv = make_float4(0.f, 0.f, 0.f, 0.f);
        if (okA) av = *(const float4*)(A + (size_t)(bm + lr) * K + k0 + lc);
        if (okB) bv = *(const float4*)(B + (size_t)(k0 + kr) * N + bn + nc4);
        __syncthreads();
        As[lc + 0][lr] = av.x; As[lc + 1][lr] = av.y; As[lc + 2][lr] = av.z; As[lc + 3][lr] = av.w;
        *(float4*)&Bs[kr][nc4] = bv;
        __syncthreads();
#pragma unroll
        for (int kk = 0; kk < 16; kk++) {
            float a0 = As[kk][tm * 4 + 0], a1 = As[kk][tm * 4 + 1];
            float a2 = As[kk][tm * 4 + 2], a3 = As[kk][tm * 4 + 3];
            float4 b = *(float4*)&Bs[kk][tn * 4];
            acc[0][0] += a0 * b.x; acc[0][1] += a0 * b.y; acc[0][2] += a0 * b.z; acc[0][3] += a0 * b.w;
            acc[1][0] += a1 * b.x; acc[1][1] += a1 * b.y; acc[1][2] += a1 * b.z; acc[1][3] += a1 * b.w;
            acc[2][0] += a2 * b.x; acc[2][1] += a2 * b.y; acc[2][2] += a2 * b.z; acc[2][3] += a2 * b.w;
            acc[3][0] += a3 * b.x; acc[3][1] += a3 * b.y; acc[3][2] += a3 * b.z; acc[3][3] += a3 * b.w;
        }
    }
#pragma unroll
    for (int i = 0; i < 4; i++) {
        int r = bm + tm * 4 + i;
        if (r >= M) continue;
        int t = r % TT;
#pragma unroll
        for (int j = 0; j < 4; j++) {
            int c = bn + tn * 4 + j;
            if (c < N) {
                float v = acc[i][j];
                if (EPI) {
                    v += addrow[(size_t)t * N + c] + bias[c];
                    v = fmaxf(v, 0.f);
                }
                C[(size_t)r * N + c] = v;
            }
        }
    }
}

// ============================================================================
// Sinkhorn (exp-domain matrix scaling), fused InstanceNorm, persistent,
// 4-CTA cluster per batch element: 100 rows of E (100x315 fp32) per CTA in SMEM.
// ============================================================================
#define SINK_FLOATS 33584
#define SINK_SMEM   (SINK_FLOATS * 4)

__global__ void __cluster_dims__(4, 1, 1) __launch_bounds__(1024, 1)
sinkhorn_kernel(float* __restrict__ s, const float* __restrict__ gamma_p,
                const float* __restrict__ beta_p) {
    extern __shared__ float sm[];
    cg::cluster_group cluster = cg::this_cluster();
    const int tid  = threadIdx.x;
    const int wid  = tid >> 5;
    const int lane = tid & 31;
    const int crank = (int)cluster.block_rank();   // 0..3
    const int batch = blockIdx.x >> 2;

    float* E   = sm;                  // 31500
    float* Cv  = sm + 31500;          // 320
    float* RU  = sm + 31820;          // 104
    float* CP  = sm + 31924;          // 948
    float* LC  = sm + 32872;          // 640 (double-buffered 2x320)
    float* RED = sm + 33512;          // 64
    float* ST  = sm + 33576;          // 8

    float* gbase = s + (size_t)batch * NN_ * TT + (size_t)crank * 100 * TT;

    // ---- phase 0: load slice + stats ----
    float psum = 0.f, psq = 0.f;
    for (int row = wid; row < 100; row += 32) {
        const float* gr = gbase + row * TT;
        float* er = E + row * TT;
        for (int t = lane; t < TT; t += 32) {
            float v = gr[t];
            er[t] = v;
            psum += v;
            psq  += v * v;
        }
    }
#pragma unroll
    for (int o = 16; o; o >>= 1) {
        psum += __shfl_xor_sync(0xffffffffu, psum, o);
        psq  += __shfl_xor_sync(0xffffffffu, psq,  o);
    }
    if (lane == 0) { RED[wid] = psum; RED[32 + wid] = psq; }
    __syncthreads();
    if (wid == 0) {
        float a = RED[lane], b = RED[32 + lane];
#pragma unroll
        for (int o = 16; o; o >>= 1) {
            a += __shfl_xor_sync(0xffffffffu, a, o);
            b += __shfl_xor_sync(0xffffffffu, b, o);
        }
        if (lane == 0) { ST[0] = a; ST[1] = b; }
    }
    cluster.sync();
    if (tid == 0) {
        float S = 0.f, Q = 0.f;
#pragma unroll
        for (int c = 0; c < 4; c++) {
            const float* r = (const float*)cluster.map_shared_rank((void*)ST, c);
            S += r[0]; Q += r[1];
        }
        const float inv = 1.0f / (float)(NN_ * TT);
        float m   = S * inv;
        float var = Q * inv - m * m;
        float istd = rsqrtf(var + 1e-5f);
        ST[2] = m;
        ST[3] = gamma_p[0] * istd;
        ST[4] = beta_p[0];
    }
    __syncthreads();
    const float mean = ST[2], gi = ST[3], bta = ST[4];

    // ---- phase 1: E = exp(norm(s)) ; init column scaling to 1 ----
    for (int row = wid; row < 100; row += 32) {
        float* er = E + row * TT;
        for (int t = lane; t < TT; t += 32)
            er[t] = expf(fmaf(er[t] - mean, gi, bta));
    }
    if (tid < TT) Cv[tid] = 1.0f;
    __syncthreads();

    // ---- phase 2: 100 sinkhorn iterations ----
    for (int k = 0; k < 100; k++) {
        // row pass: ru[n] = 1 / sum_t E[n,t]*Cv[t]   (local rows)
        for (int row = wid; row < 100; row += 32) {
            const float* er = E + row * TT;
            float acc = 0.f;
            for (int t = lane; t < TT; t += 32) acc += er[t] * Cv[t];
#pragma unroll
            for (int o = 16; o; o >>= 1) acc += __shfl_xor_sync(0xffffffffu, acc, o);
            if (lane == 0) RU[row] = 1.0f / acc;
        }
        __syncthreads();
        // col pass partials over local rows (3 row-chunks per column)
        if (tid < 3 * TT) {
            int p = tid / TT;                 // 0..2
            int t = tid - p * TT;
            int r0 = (p == 0) ? 0 : (33 * p + 1);
            int r1 = r0 + ((p == 0) ? 34 : 33);
            float acc = 0.f;
            for (int n = r0; n < r1; n++) acc += E[n * TT + t] * RU[n];
            CP[p * TT + t] = acc;
        }
        __syncthreads();
        const int buf = (k & 1) * 320;
        if (tid < TT) LC[buf + tid] = CP[tid] + CP[TT + tid] + CP[2 * TT + tid];
        cluster.sync();
        if (tid < TT) {
            float tot = 0.f;
#pragma unroll
            for (int c = 0; c < 4; c++) {
                const float* r = (const float*)cluster.map_shared_rank((void*)LC, c);
                tot += r[buf + tid];
            }
            Cv[tid] = 1.0f / tot;
        }
        __syncthreads();
    }

    // ---- phase 3: write s1 = E * ru * cv ----
    for (int row = wid; row < 100; row += 32) {
        const float r = RU[row];
        const float* er = E + row * TT;
        float* gr = gbase + row * TT;
        for (int t = lane; t < TT; t += 32)
            gr[t] = er[t] * r * Cv[t];
    }
    cluster.sync();   // keep SMEM alive until all cluster reads are done
}

// ============================================================================
// head: pred[i] = sum_h h[i,h] * Wo[h] + bo    (one warp per output row)
// ============================================================================
__global__ void head_kernel(const float* __restrict__ h, const float* __restrict__ Wo,
                            const float* __restrict__ bo, float* __restrict__ out, int total) {
    int gwarp = (blockIdx.x * blockDim.x + threadIdx.x) >> 5;
    int lane = threadIdx.x & 31;
    if (gwarp >= total) return;
    const float* hp = h + (size_t)gwarp * HH;
    float acc = 0.f;
#pragma unroll
    for (int i = lane; i < HH; i += 32) acc += hp[i] * Wo[i];
#pragma unroll
    for (int o = 16; o; o >>= 1) acc += __shfl_xor_sync(0xffffffffu, acc, o);
    if (lane == 0) out[gwarp] = acc + bo[0];
}

// ============================================================================
extern "C" void kernel_launch(void* const* d_in, const int* in_sizes, int n_in,
                              void* d_out, int out_size) {
    (void)in_sizes; (void)n_in; (void)out_size;
    const float* features = (const float*)d_in[0];   // [B, N, D]
    const float* text     = (const float*)d_in[1];   // [T, D]
    const float* Amat     = (const float*)d_in[2];   // [D, D]
    const float* gamma    = (const float*)d_in[3];   // scalar
    const float* beta     = (const float*)d_in[4];   // scalar
    const float* Wh       = (const float*)d_in[5];   // [2D, H]
    const float* bh       = (const float*)d_in[6];   // [H]
    const float* Wo       = (const float*)d_in[7];   // [H, 1]
    const float* bo       = (const float*)d_in[8];   // [1]
    float* out = (float*)d_out;                      // [B, T]

    float *tA, *sbuf, *f1, *th, *hbuf;
    cudaGetSymbolAddress((void**)&tA,   g_tA);
    cudaGetSymbolAddress((void**)&sbuf, g_s);
    cudaGetSymbolAddress((void**)&f1,   g_f1);
    cudaGetSymbolAddress((void**)&th,   g_th);
    cudaGetSymbolAddress((void**)&hbuf, g_h);

    cudaFuncSetAttribute(sinkhorn_kernel,
                         cudaFuncAttributeMaxDynamicSharedMemorySize, SINK_SMEM);

    dim3 b256(256);

    // tA[t,d] = sum_e text[t,e] * A[d,e]
    gemm_nt_kernel<<<dim3((TT + 63) / 64, DD / 64), b256>>>(text, Amat, tA, TT, DD, DD, DD);

    // s[b*n, t] = sum_d features[b,n,d] * tA[t,d]
    gemm_nt_kernel<<<dim3((BB * NN_) / 64, (TT + 63) / 64), b256>>>(
        features, tA, sbuf, BB * NN_, TT, DD, TT);

    // instance-norm + 100 sinkhorn iterations, s -> s1 in place
    sinkhorn_kernel<<<BB * 4, 1024, SINK_SMEM>>>(sbuf, gamma, beta);

    // features1[b,t,d] = sum_n s1[b,n,t] * features[b,n,d]
    gemm_tn_kernel<<<dim3((TT + 63) / 64, DD / 64, BB), b256>>>(
        sbuf, features, f1, TT, DD, NN_, TT, DD, DD,
        (long long)NN_ * TT, (long long)NN_ * DD, (long long)TT * DD);

    // th[t,h] = sum_e text[t,e] * Wh[D+e, h]
    gemm_nn_kernel<0><<<dim3((TT + 63) / 64, HH / 64), b256>>>(
        text, Wh + (size_t)DD * HH, th, TT, HH, DD, nullptr, nullptr);

    // h = relu(f1 @ Wh_top + th + bh)
    gemm_nn_kernel<1><<<dim3((BB * TT + 63) / 64, HH / 64), b256>>>(
        f1, Wh, hbuf, BB * TT, HH, DD, th, bh);

    // pred = h @ Wo + bo
    head_kernel<<<(BB * TT * 32 + 255) / 256, 256>>>(hbuf, Wo, bo, out, BB * TT);
}